// round 3
// baseline (speedup 1.0000x reference)
#include <cuda_runtime.h>
#include <cuda_fp16.h>
#include <cstdint>

// ---------------------------------------------------------------------------
// Range_Fourier_Net: batched complex DFT == one real GEMM (HMMA mma.sync path;
// tcgen05 unavailable: harness ptxas target is plain sm_103).
//   A = [x_r | x_i]            (M=65536, K=512)  fp32 -> fp16 fused into smem fill
//   B[n][k] from +-W_r/+-W_i   (N=512, K=512)    fp16, prebuilt per launch
//   C = [y_r | y_i]            (M, 512) fp32 -> out[2][M][256]
// 128x128 CTA tile, K chunks of 64, double-buffered smem, cp.async for B,
// ldmatrix + mma.sync.m16n8k16 row.col, 8 warps in 2x4 layout (64x32 each).
// ---------------------------------------------------------------------------

#define MTOT   65536
#define KTOT   512
#define NBIG   512
#define TILE_M 128
#define TILE_N 128
#define KC     64
#define NCHUNK 8

#define SWZ(o) ((o) ^ (((o) >> 3) & 0x70))

// SMEM (bytes): A[2][128][64]f16, B[2][128][64]f16
#define SM_A    0
#define SM_B    (2 * 16384)
#define SMEM_BYTES (4 * 16384)

__device__ __half g_Wbig[NBIG * KTOT];   // [n][k], K-major rows

// ---------------------------------------------------------------------------
static __device__ __forceinline__ uint32_t smem_u32(const void* p) {
    uint32_t a;
    asm("{ .reg .u64 t; cvta.to.shared.u64 t, %1; cvt.u32.u64 %0, t; }"
        : "=r"(a) : "l"(p));
    return a;
}

#define CP_ASYNC16(dst, src) \
    asm volatile("cp.async.cg.shared.global [%0], [%1], 16;" \
                 :: "r"(dst), "l"(src) : "memory")
#define CP_COMMIT() asm volatile("cp.async.commit_group;" ::: "memory")
#define CP_WAIT0()  asm volatile("cp.async.wait_group 0;" ::: "memory")

#define LDSM_X4(r0, r1, r2, r3, addr)                                        \
    asm volatile("ldmatrix.sync.aligned.m8n8.x4.shared.b16 {%0,%1,%2,%3}, [%4];" \
                 : "=r"(r0), "=r"(r1), "=r"(r2), "=r"(r3) : "r"(addr))

#define MMA16816(d, a0, a1, a2, a3, b0, b1)                                  \
    asm volatile("mma.sync.aligned.m16n8k16.row.col.f32.f16.f16.f32 "        \
                 "{%0,%1,%2,%3}, {%4,%5,%6,%7}, {%8,%9}, {%0,%1,%2,%3};"     \
                 : "+f"((d)[0]), "+f"((d)[1]), "+f"((d)[2]), "+f"((d)[3])    \
                 : "r"(a0), "r"(a1), "r"(a2), "r"(a3), "r"(b0), "r"(b1))

// ---------------------------------------------------------------------------
// Prep: build fp16 B matrix [n][k] (K-major) from W_r/W_i.
//   n<256 (real plane):  B[n] = [  W_r[n] | -W_i[n] ]
//   n>=256 (imag plane): B[n] = [  W_i[n']|  W_r[n']]
// ---------------------------------------------------------------------------
__global__ void prep_w_kernel(const float* __restrict__ wr, const float* __restrict__ wi) {
    int idx = blockIdx.x * blockDim.x + threadIdx.x;
    if (idx >= NBIG * KTOT) return;
    int n = idx >> 9;
    int k = idx & 511;
    float v;
    if (n < 256) {
        v = (k < 256) ? wr[n * 256 + k] : -wi[n * 256 + (k - 256)];
    } else {
        v = (k < 256) ? wi[(n - 256) * 256 + k] : wr[(n - 256) * 256 + (k - 256)];
    }
    g_Wbig[idx] = __float2half_rn(v);
}

// ---------------------------------------------------------------------------
__global__ void __launch_bounds__(256, 2)
dft_gemm_kernel(const float* __restrict__ xr, const float* __restrict__ xi,
                float* __restrict__ out) {
    extern __shared__ char smem[];
    const uint32_t sb = smem_u32(smem);
    const int tid = threadIdx.x;
    const int wid = tid >> 5;
    const int lid = tid & 31;
    const int warp_m = wid & 1;        // 2 warp-rows  * 64 m
    const int warp_n = wid >> 1;       // 4 warp-cols  * 32 n
    const int n0 = blockIdx.x * TILE_N;   // n fastest: 4 n-tiles of one m-block co-resident
    const int m0 = blockIdx.y * TILE_M;

    float acc[4][4][4];                // [mfrag][nfrag][reg]
#pragma unroll
    for (int i = 0; i < 4; i++)
#pragma unroll
        for (int j = 0; j < 4; j++)
#pragma unroll
            for (int r = 0; r < 4; r++) acc[i][j][r] = 0.0f;

    // segment ownership for loads: 1024 16B-segments per tile, 4 per thread
    const int rl0  = tid >> 3;         // rows tid/8, +32, +64, +96
    const int seg0 = tid & 7;          // 16B segment within 128B row

    // ---- chunk loader ----
    auto load_chunk = [&](int c, int stage) {
        const float* src = (c < 4) ? xr : xi;
        const int colb = (c & 3) * KC;
        const uint32_t a_off = sb + SM_A + stage * 16384;
        const uint32_t b_off = sb + SM_B + stage * 16384;
        // B via cp.async (fp16 in gmem already)
#pragma unroll
        for (int j = 0; j < 4; j++) {
            int rl = rl0 + j * 32;
            const __half* g = g_Wbig + (size_t)(n0 + rl) * KTOT + c * KC + seg0 * 8;
            CP_ASYNC16(b_off + SWZ((uint32_t)(rl * 128 + seg0 * 16)), g);
        }
        CP_COMMIT();
        // A via LDG fp32 -> cvt -> STS fp16
#pragma unroll
        for (int j = 0; j < 4; j++) {
            int rl = rl0 + j * 32;
            const float4* p =
                reinterpret_cast<const float4*>(src + (size_t)(m0 + rl) * 256 + colb + seg0 * 8);
            float4 f0 = p[0], f1 = p[1];
            __half2 h0 = __float22half2_rn(make_float2(f0.x, f0.y));
            __half2 h1 = __float22half2_rn(make_float2(f0.z, f0.w));
            __half2 h2 = __float22half2_rn(make_float2(f1.x, f1.y));
            __half2 h3 = __float22half2_rn(make_float2(f1.z, f1.w));
            uint4 v;
            v.x = *reinterpret_cast<uint32_t*>(&h0);
            v.y = *reinterpret_cast<uint32_t*>(&h1);
            v.z = *reinterpret_cast<uint32_t*>(&h2);
            v.w = *reinterpret_cast<uint32_t*>(&h3);
            *reinterpret_cast<uint4*>(smem + SM_A + stage * 16384 +
                                      SWZ((uint32_t)(rl * 128 + seg0 * 16))) = v;
        }
    };

    // ldmatrix lane-address components (bytes within tile)
    const uint32_t a_lrow = (uint32_t)(warp_m * 64 + (lid & 15));      // + i*16
    const uint32_t a_lkb  = (uint32_t)((lid >> 4) * 16);               // + ks*32
    const uint32_t b_lrow = (uint32_t)(warp_n * 32 + (lid >> 4) * 8 + (lid & 7)); // + j*16
    const uint32_t b_lkb  = (uint32_t)(((lid >> 3) & 1) * 16);         // + ks*32

    load_chunk(0, 0);

    for (int c = 0; c < NCHUNK; c++) {
        CP_WAIT0();
        __syncthreads();               // buf[c&1] ready; buf[(c+1)&1] free
        if (c + 1 < NCHUNK) load_chunk(c + 1, (c + 1) & 1);

        const uint32_t a_base = sb + SM_A + (c & 1) * 16384;
        const uint32_t b_base = sb + SM_B + (c & 1) * 16384;
#pragma unroll
        for (int ks = 0; ks < 4; ks++) {
            uint32_t a[4][4];
#pragma unroll
            for (int i = 0; i < 4; i++) {
                uint32_t addr = a_base +
                    SWZ((a_lrow + i * 16) * 128 + ks * 32 + a_lkb);
                LDSM_X4(a[i][0], a[i][1], a[i][2], a[i][3], addr);
            }
            uint32_t b[8];             // 4 nfrags x 2 regs
#pragma unroll
            for (int j = 0; j < 2; j++) {
                uint32_t addr = b_base +
                    SWZ((b_lrow + j * 16) * 128 + ks * 32 + b_lkb);
                LDSM_X4(b[j * 4 + 0], b[j * 4 + 1], b[j * 4 + 2], b[j * 4 + 3], addr);
            }
#pragma unroll
            for (int i = 0; i < 4; i++)
#pragma unroll
                for (int j = 0; j < 4; j++)
                    MMA16816(acc[i][j], a[i][0], a[i][1], a[i][2], a[i][3],
                             b[j * 2 + 0], b[j * 2 + 1]);
        }
        __syncthreads();               // compute(c) done before stores into buf[c&1] at c+2
    }

    // ---- epilogue: direct STG from accumulators ----
    {
        const int plane = (n0 >= 256);
        const int colp = (n0 & 255) + warp_n * 32 + (lid & 3) * 2;
        const int rbase = m0 + warp_m * 64 + (lid >> 2);
        float* outp = out + (size_t)plane * ((size_t)MTOT * 256);
#pragma unroll
        for (int i = 0; i < 4; i++) {
#pragma unroll
            for (int j = 0; j < 4; j++) {
                float2 lo = make_float2(acc[i][j][0], acc[i][j][1]);
                float2 hi = make_float2(acc[i][j][2], acc[i][j][3]);
                size_t r0 = (size_t)(rbase + i * 16) * 256 + colp + j * 8;
                *reinterpret_cast<float2*>(outp + r0) = lo;
                *reinterpret_cast<float2*>(outp + r0 + 8 * 256) = hi;
            }
        }
    }
}

// ---------------------------------------------------------------------------
extern "C" void kernel_launch(void* const* d_in, const int* in_sizes, int n_in,
                              void* d_out, int out_size) {
    const float* xr = (const float*)d_in[0];
    const float* xi = (const float*)d_in[1];
    const float* wr = (const float*)d_in[2];
    const float* wi = (const float*)d_in[3];
    float* out = (float*)d_out;

    prep_w_kernel<<<(NBIG * KTOT) / 256, 256>>>(wr, wi);

    cudaFuncSetAttribute(dft_gemm_kernel,
                         cudaFuncAttributeMaxDynamicSharedMemorySize, SMEM_BYTES);
    dim3 grid(NBIG / TILE_N, MTOT / TILE_M);   // (4, 512), n-tiles fastest
    dft_gemm_kernel<<<grid, 256, SMEM_BYTES>>>(xr, xi, out);
}

// round 5
// speedup vs baseline: 1.1503x; 1.1503x over previous
#include <cuda_runtime.h>
#include <cuda_fp16.h>
#include <cstdint>

// ---------------------------------------------------------------------------
// Range_Fourier_Net: batched complex DFT == one real GEMM (HMMA mma.sync path).
//   A = [x_r | x_i]            (M=65536, K=512)  fp32 -> fp16 fused into fill
//   B[n][k] from +-W_r/+-W_i   (N=512, K=512)    fp16, prebuilt per launch
//   C = [y_r | y_i]            (M, 512) fp32 -> out[2][M][256]
// 128x128 CTA tile, 4 warps of 64x64, K chunks of 64, double-buffered smem.
// Register-staged A loads overlap MMA; cp.async for B.
// ---------------------------------------------------------------------------

#define MTOT   65536
#define KTOT   512
#define NBIG   512
#define TILE_M 128
#define TILE_N 128
#define KC     64
#define NCHUNK 8

#define SWZ(o) ((o) ^ (((o) >> 3) & 0x70))

// SMEM (bytes): A[2][128][64]f16 then B[2][128][64]f16
#define SM_A    0
#define SM_B    (2 * 16384)
#define SMEM_BYTES (4 * 16384)

__device__ __half g_Wbig[NBIG * KTOT];   // [n][k], K-major rows

// ---------------------------------------------------------------------------
static __device__ __forceinline__ uint32_t smem_u32(const void* p) {
    uint32_t a;
    asm("{ .reg .u64 t; cvta.to.shared.u64 t, %1; cvt.u32.u64 %0, t; }"
        : "=r"(a) : "l"(p));
    return a;
}

#define CP_ASYNC16(dst, src) \
    asm volatile("cp.async.cg.shared.global [%0], [%1], 16;" \
                 :: "r"(dst), "l"(src) : "memory")
#define CP_COMMIT() asm volatile("cp.async.commit_group;" ::: "memory")
#define CP_WAIT0()  asm volatile("cp.async.wait_group 0;" ::: "memory")

#define LDSM_X4(r0, r1, r2, r3, addr)                                        \
    asm volatile("ldmatrix.sync.aligned.m8n8.x4.shared.b16 {%0,%1,%2,%3}, [%4];" \
                 : "=r"(r0), "=r"(r1), "=r"(r2), "=r"(r3) : "r"(addr))

#define MMA16816(d, a0, a1, a2, a3, b0, b1)                                  \
    asm volatile("mma.sync.aligned.m16n8k16.row.col.f32.f16.f16.f32 "        \
                 "{%0,%1,%2,%3}, {%4,%5,%6,%7}, {%8,%9}, {%0,%1,%2,%3};"     \
                 : "+f"((d)[0]), "+f"((d)[1]), "+f"((d)[2]), "+f"((d)[3])    \
                 : "r"(a0), "r"(a1), "r"(a2), "r"(a3), "r"(b0), "r"(b1))

// ---------------------------------------------------------------------------
// Prep: build fp16 B matrix [n][k] (K-major) from W_r/W_i.
//   n<256 (real plane):  B[n] = [  W_r[n] | -W_i[n] ]
//   n>=256 (imag plane): B[n] = [  W_i[n']|  W_r[n']]
// ---------------------------------------------------------------------------
__global__ void prep_w_kernel(const float* __restrict__ wr, const float* __restrict__ wi) {
    int idx = blockIdx.x * blockDim.x + threadIdx.x;
    if (idx >= NBIG * KTOT) return;
    int n = idx >> 9;
    int k = idx & 511;
    float v;
    if (n < 256) {
        v = (k < 256) ? wr[n * 256 + k] : -wi[n * 256 + (k - 256)];
    } else {
        v = (k < 256) ? wi[(n - 256) * 256 + k] : wr[(n - 256) * 256 + (k - 256)];
    }
    g_Wbig[idx] = __float2half_rn(v);
}

// ---------------------------------------------------------------------------
__global__ void __launch_bounds__(128, 2)
dft_gemm_kernel(const float* __restrict__ xr, const float* __restrict__ xi,
                float* __restrict__ out) {
    extern __shared__ char smem[];
    const uint32_t sb = smem_u32(smem);
    const int tid = threadIdx.x;
    const int wid = tid >> 5;
    const int lid = tid & 31;
    const int warp_m = wid & 1;        // 2 warp-rows * 64 m
    const int warp_n = wid >> 1;       // 2 warp-cols * 64 n
    const int n0 = blockIdx.x * TILE_N;   // n fastest: 4 n-tiles of one m-block co-resident
    const int m0 = blockIdx.y * TILE_M;

    float acc[4][8][4];                // [mfrag 16][nfrag 8][reg]
#pragma unroll
    for (int i = 0; i < 4; i++)
#pragma unroll
        for (int j = 0; j < 8; j++)
#pragma unroll
            for (int r = 0; r < 4; r++) acc[i][j][r] = 0.0f;

    // load ownership: 1024 16B-segments per tile, 8 per thread (128 threads)
    const int rlb  = tid >> 3;         // base row, rows rlb + w*16, w=0..7
    const int seg0 = tid & 7;          // 16B segment within 128B row

    // ---- B chunk: 8 cp.async per thread ----
    auto load_B = [&](int c, int stage) {
        const uint32_t b_off = sb + SM_B + stage * 16384;
#pragma unroll
        for (int w = 0; w < 8; w++) {
            int rl = rlb + w * 16;
            const __half* g = g_Wbig + (size_t)(n0 + rl) * KTOT + c * KC + seg0 * 8;
            CP_ASYNC16(b_off + SWZ((uint32_t)(rl * 128 + seg0 * 16)), g);
        }
    };

    // ---- A chunk in 2 waves of 4 segments (8 LDG.128 staged in f[8]) ----
    auto ldgA_wave = [&](int c, int w0, float4* f) {
        const float* src = (c < 4) ? xr : xi;
        const int colb = (c & 3) * KC;
#pragma unroll
        for (int q = 0; q < 4; q++) {
            int rl = rlb + (w0 + q) * 16;
            const float4* p = reinterpret_cast<const float4*>(
                src + (size_t)(m0 + rl) * 256 + colb + seg0 * 8);
            f[q * 2] = p[0];
            f[q * 2 + 1] = p[1];
        }
    };
    auto stsA_wave = [&](int stage, int w0, const float4* f) {
#pragma unroll
        for (int q = 0; q < 4; q++) {
            int rl = rlb + (w0 + q) * 16;
            __half2 h0 = __float22half2_rn(make_float2(f[q*2].x, f[q*2].y));
            __half2 h1 = __float22half2_rn(make_float2(f[q*2].z, f[q*2].w));
            __half2 h2 = __float22half2_rn(make_float2(f[q*2+1].x, f[q*2+1].y));
            __half2 h3 = __float22half2_rn(make_float2(f[q*2+1].z, f[q*2+1].w));
            uint4 v;
            v.x = *reinterpret_cast<uint32_t*>(&h0);
            v.y = *reinterpret_cast<uint32_t*>(&h1);
            v.z = *reinterpret_cast<uint32_t*>(&h2);
            v.w = *reinterpret_cast<uint32_t*>(&h3);
            *reinterpret_cast<uint4*>(smem + SM_A + stage * 16384 +
                                      SWZ((uint32_t)(rl * 128 + seg0 * 16))) = v;
        }
    };

    // ldmatrix lane-address components (bytes within tile)
    const uint32_t a_lrow = (uint32_t)(warp_m * 64 + (lid & 15));              // + i*16
    const uint32_t a_lkb  = (uint32_t)((lid >> 4) * 16);                       // + ks*32
    const uint32_t b_lrow = (uint32_t)(warp_n * 64 + (lid >> 4) * 8 + (lid & 7)); // + j*16
    const uint32_t b_lkb  = (uint32_t)(((lid >> 3) & 1) * 16);                 // + ks*32

    auto mma_ks = [&](int ks, uint32_t a_base, uint32_t b_base) {
        uint32_t a[4][4];
#pragma unroll
        for (int i = 0; i < 4; i++) {
            uint32_t addr = a_base + SWZ((a_lrow + i * 16) * 128 + ks * 32 + a_lkb);
            LDSM_X4(a[i][0], a[i][1], a[i][2], a[i][3], addr);
        }
        uint32_t b[16];                 // 8 nfrags x 2 regs
#pragma unroll
        for (int j = 0; j < 4; j++) {
            uint32_t addr = b_base + SWZ((b_lrow + j * 16) * 128 + ks * 32 + b_lkb);
            LDSM_X4(b[j*4+0], b[j*4+1], b[j*4+2], b[j*4+3], addr);
        }
#pragma unroll
        for (int i = 0; i < 4; i++)
#pragma unroll
            for (int j = 0; j < 8; j++)
                MMA16816(acc[i][j], a[i][0], a[i][1], a[i][2], a[i][3],
                         b[j*2+0], b[j*2+1]);
    };

    // ---- prologue: chunk 0 ----
    load_B(0, 0);
    CP_COMMIT();
    {
        float4 f[8];
        ldgA_wave(0, 0, f); stsA_wave(0, 0, f);
        ldgA_wave(0, 4, f); stsA_wave(0, 4, f);
    }

    float4 fst[8];   // A staging for next chunk
    for (int c = 0; c < NCHUNK; c++) {
        CP_WAIT0();
        __syncthreads();               // stage c&1 fully ready for all warps
        const uint32_t a_base = sb + SM_A + (c & 1) * 16384;
        const uint32_t b_base = sb + SM_B + (c & 1) * 16384;
        const int sn = (c + 1) & 1;
        const bool more = (c + 1 < NCHUNK);

        if (more) {
            load_B(c + 1, sn);         // async into free stage
            CP_COMMIT();
            ldgA_wave(c + 1, 0, fst);  // LDG latency overlaps MMAs below
        }
        mma_ks(0, a_base, b_base);
        if (more) {
            stsA_wave(sn, 0, fst);
            ldgA_wave(c + 1, 4, fst);
        }
        mma_ks(1, a_base, b_base);
        mma_ks(2, a_base, b_base);
        if (more) stsA_wave(sn, 4, fst);
        mma_ks(3, a_base, b_base);
        __syncthreads();               // reads of stage c&1 done before c+2 writes it
    }

    // ---- epilogue: direct STG from accumulators ----
    {
        const int plane = (n0 >= 256);
        const int colp = (n0 & 255) + warp_n * 64 + (lid & 3) * 2;
        const int rbase = m0 + warp_m * 64 + (lid >> 2);
        float* outp = out + (size_t)plane * ((size_t)MTOT * 256);
#pragma unroll
        for (int i = 0; i < 4; i++) {
#pragma unroll
            for (int j = 0; j < 8; j++) {
                float2 lo = make_float2(acc[i][j][0], acc[i][j][1]);
                float2 hi = make_float2(acc[i][j][2], acc[i][j][3]);
                size_t r0 = (size_t)(rbase + i * 16) * 256 + colp + j * 8;
                *reinterpret_cast<float2*>(outp + r0) = lo;
                *reinterpret_cast<float2*>(outp + r0 + 8 * 256) = hi;
            }
        }
    }
}

// ---------------------------------------------------------------------------
extern "C" void kernel_launch(void* const* d_in, const int* in_sizes, int n_in,
                              void* d_out, int out_size) {
    const float* xr = (const float*)d_in[0];
    const float* xi = (const float*)d_in[1];
    const float* wr = (const float*)d_in[2];
    const float* wi = (const float*)d_in[3];
    float* out = (float*)d_out;

    prep_w_kernel<<<(NBIG * KTOT) / 256, 256>>>(wr, wi);

    cudaFuncSetAttribute(dft_gemm_kernel,
                         cudaFuncAttributeMaxDynamicSharedMemorySize, SMEM_BYTES);
    dim3 grid(NBIG / TILE_N, MTOT / TILE_M);   // (4, 512), n-tiles fastest
    dft_gemm_kernel<<<grid, 128, SMEM_BYTES>>>(xr, xi, out);
}